// round 6
// baseline (speedup 1.0000x reference)
#include <cuda_runtime.h>
#include <cuda_fp16.h>
#include <cstdint>
#include <cstddef>

#define DEVINL __device__ __forceinline__

// ---------------- problem dims ----------------
constexpr int Bdim = 4, Tdim = 256, Udim = 64, Ddim = 512, Jdim = 1024, Vdim = 1024;
constexpr int Mtot = Bdim * Tdim * Udim;  // 65536

// ---------------- device scratch (allocs forbidden) ----------------
__device__ float g_enc_out[Bdim * Tdim * Jdim];   // 4 MB  [1024, 1024]
__device__ float g_pred_out[Bdim * Udim * Jdim];  // 1 MB  [256, 1024]
__device__ __half g_Wth[Vdim * Jdim];             // 2 MB  W_out^T, fp16
__device__ __half g_Ah[(size_t)Mtot * Jdim];      // 134 MB  tanh(joint), fp16

// ---------------- PTX helpers (baseline ISA, sm_80-level) ----------------
DEVINL uint32_t smem_u32(const void* p) {
    uint32_t a;
    asm("{ .reg .u64 t; cvta.to.shared.u64 t, %1; cvt.u32.u64 %0, t; }" : "=r"(a) : "l"(p));
    return a;
}
DEVINL void cp_async16(uint32_t dst, const void* src) {
    asm volatile("cp.async.cg.shared.global [%0], [%1], 16;" :: "r"(dst), "l"(src) : "memory");
}
DEVINL void cp_commit() { asm volatile("cp.async.commit_group;" ::: "memory"); }
DEVINL void cp_wait2() { asm volatile("cp.async.wait_group 2;" ::: "memory"); }

DEVINL void ldsm_x4(uint32_t& r0, uint32_t& r1, uint32_t& r2, uint32_t& r3, uint32_t addr) {
    asm volatile("ldmatrix.sync.aligned.m8n8.x4.shared.b16 {%0,%1,%2,%3}, [%4];"
                 : "=r"(r0), "=r"(r1), "=r"(r2), "=r"(r3) : "r"(addr));
}
DEVINL void mma_fp16(float& c0, float& c1, float& c2, float& c3,
                     uint32_t a0, uint32_t a1, uint32_t a2, uint32_t a3,
                     uint32_t b0, uint32_t b1) {
    asm volatile(
        "mma.sync.aligned.m16n8k16.row.col.f32.f16.f16.f32 "
        "{%0,%1,%2,%3}, {%4,%5,%6,%7}, {%8,%9}, {%0,%1,%2,%3};"
        : "+f"(c0), "+f"(c1), "+f"(c2), "+f"(c3)
        : "r"(a0), "r"(a1), "r"(a2), "r"(a3), "r"(b0), "r"(b1));
}

// accurate tanh (ex2.approx + rcp.approx, ~1e-6 rel)
DEVINL float tanh_fast(float x) {
    x = fminf(20.0f, fmaxf(-20.0f, x));
    float e;
    asm("ex2.approx.f32 %0, %1;" : "=f"(e) : "f"(x * 2.885390081777927f)); // 2*log2(e)
    float r;
    asm("rcp.approx.f32 %0, %1;" : "=f"(r) : "f"(e + 1.0f));
    return (e - 1.0f) * r;
}
DEVINL uint32_t pack_h2(float lo, float hi) {
    __half2 h = __floats2half2_rn(lo, hi);
    return *(uint32_t*)&h;
}

// ================= kernel 1: fp32 projection GEMM (C = X @ W + bias) =================
__global__ __launch_bounds__(256) void proj_kernel(const float* __restrict__ X,
                                                   const float* __restrict__ W,
                                                   const float* __restrict__ bias,
                                                   int which) {
    float* __restrict__ C = which ? g_pred_out : g_enc_out;
    __shared__ float As[16][68];
    __shared__ float Bs[16][64];
    int tid = threadIdx.x;
    int m0 = blockIdx.y * 64;
    int n0 = blockIdx.x * 64;
    int ty = tid >> 4, tx = tid & 15;
    int a_m = tid >> 2, a_kq = tid & 3;
    int b_k = tid >> 4, b_nq = tid & 15;

    float acc[4][4];
#pragma unroll
    for (int i = 0; i < 4; ++i)
#pragma unroll
        for (int j = 0; j < 4; ++j) acc[i][j] = 0.0f;

    for (int k0 = 0; k0 < Ddim; k0 += 16) {
        float4 av = *(const float4*)(X + (size_t)(m0 + a_m) * Ddim + k0 + a_kq * 4);
        float4 bv = *(const float4*)(W + (size_t)(k0 + b_k) * Jdim + n0 + b_nq * 4);
        __syncthreads();
        As[a_kq * 4 + 0][a_m] = av.x;
        As[a_kq * 4 + 1][a_m] = av.y;
        As[a_kq * 4 + 2][a_m] = av.z;
        As[a_kq * 4 + 3][a_m] = av.w;
        *(float4*)&Bs[b_k][b_nq * 4] = bv;
        __syncthreads();
#pragma unroll
        for (int kk = 0; kk < 16; ++kk) {
            float a[4], b[4];
#pragma unroll
            for (int i = 0; i < 4; ++i) a[i] = As[kk][ty * 4 + i];
            float4 b4 = *(const float4*)&Bs[kk][tx * 4];
            b[0] = b4.x; b[1] = b4.y; b[2] = b4.z; b[3] = b4.w;
#pragma unroll
            for (int i = 0; i < 4; ++i)
#pragma unroll
                for (int j = 0; j < 4; ++j) acc[i][j] = fmaf(a[i], b[j], acc[i][j]);
        }
    }
#pragma unroll
    for (int i = 0; i < 4; ++i) {
#pragma unroll
        for (int j = 0; j < 4; ++j) {
            int n = n0 + tx * 4 + j;
            C[(size_t)(m0 + ty * 4 + i) * Jdim + n] = acc[i][j] + bias[n];
        }
    }
}

// ======== kernel 2: transpose W_out [J,V] -> g_Wth [V,J] in fp16 ========
__global__ __launch_bounds__(256) void transpose_h_kernel(const float* __restrict__ W) {
    __shared__ float tile[32][33];
    int v0 = blockIdx.x * 32;
    int j0 = blockIdx.y * 32;
    int tx = threadIdx.x & 31;
    int ty = threadIdx.x >> 5;  // 0..7
#pragma unroll
    for (int i = 0; i < 32; i += 8)
        tile[ty + i][tx] = W[(size_t)(j0 + ty + i) * Vdim + v0 + tx];
    __syncthreads();
#pragma unroll
    for (int i = 0; i < 32; i += 8)
        g_Wth[(size_t)(v0 + ty + i) * Jdim + j0 + tx] = __float2half_rn(tile[tx][ty + i]);
}

// ======== kernel 3: A_h[m][k] = fp16(tanh(enc_out[b,t,k] + pred_out[b,u,k])) ========
// one thread = 8 consecutive k (one uint4 store). 32768 blocks x 256 threads.
__global__ __launch_bounds__(256) void tanh_pre_kernel() {
    size_t idx = (size_t)blockIdx.x * 256 + threadIdx.x;  // octet index
    int m = (int)(idx >> 7);
    int kc = ((int)idx & 127) * 8;
    int b = m >> 14, t = (m >> 6) & (Tdim - 1), u = m & (Udim - 1);
    const float* e = g_enc_out + ((size_t)((b << 8) + t) << 10) + kc;
    const float* p = g_pred_out + ((size_t)((b << 6) + u) << 10) + kc;
    float4 e0 = *(const float4*)e;
    float4 p0 = *(const float4*)p;
    float4 e1 = *(const float4*)(e + 4);
    float4 p1 = *(const float4*)(p + 4);
    uint4 o;
    o.x = pack_h2(tanh_fast(e0.x + p0.x), tanh_fast(e0.y + p0.y));
    o.y = pack_h2(tanh_fast(e0.z + p0.z), tanh_fast(e0.w + p0.w));
    o.z = pack_h2(tanh_fast(e1.x + p1.x), tanh_fast(e1.y + p1.y));
    o.w = pack_h2(tanh_fast(e1.z + p1.z), tanh_fast(e1.w + p1.w));
    *(uint4*)(g_Ah + ((size_t)m << 10) + kc) = o;
}

// ================= kernel 4: pure fp16 GEMM  out = A_h @ Wt^T + bias =================
// CTA tile 128(M) x 128(N), 128 threads = 4 warps (2M x 2N), warp tile 64x64.
// 4-stage cp.async(.cg) pipeline; 2 CTAs per SM.
constexpr int ARSTR = 80;                        // bytes per smem row (64B data + pad)
constexpr int ABYTES = 128 * ARSTR;              // 10240
constexpr int BBYTES = 128 * ARSTR;              // 10240
constexpr int STG_BYTES = ABYTES + BBYTES;       // 20480
constexpr int NSTAGE = 4;
constexpr int OFF_STG = 1024;
constexpr int GEMM_SMEM = OFF_STG + NSTAGE * STG_BYTES;  // 82944

__global__ __launch_bounds__(128, 2) void gemm_kernel(
    const float* __restrict__ b_out, float* __restrict__ out) {
    extern __shared__ char smem[];
    uint32_t sb = smem_u32(smem);
    float* bias_s = (float*)smem;

    int tid = threadIdx.x;
    int lane = tid & 31;
    int wid = tid >> 5;       // 0..3
    int wm = wid >> 1;        // 0..1
    int wn = wid & 1;         // 0..1

    int n0 = blockIdx.x << 7;          // N-tile (fast dim -> A reuse in L2)
    int m0 = blockIdx.y << 7;          // M-tile

    bias_s[tid] = b_out[n0 + tid];

    // ---- producer addressing: thread owns one row's 64B per chunk (4x16B) ----
    const __half* asrc = g_Ah + ((size_t)(m0 + tid) << 10);
    const __half* bsrc = g_Wth + ((size_t)(n0 + tid) << 10);
    uint32_t a_sts = (uint32_t)tid * ARSTR;
    uint32_t b_sts = ABYTES + (uint32_t)tid * ARSTR;

    // ---- consumer LDSM per-lane offsets ----
    uint32_t a_off[4], b_off[4];
#pragma unroll
    for (int mt = 0; mt < 4; ++mt) {
        int row = wm * 64 + mt * 16 + (lane & 15);
        a_off[mt] = (uint32_t)row * ARSTR + (uint32_t)(lane >> 4) * 16;
    }
#pragma unroll
    for (int g = 0; g < 4; ++g) {
        int row = wn * 64 + g * 16 + (lane & 7) + ((lane >> 4) & 1) * 8;
        b_off[g] = ABYTES + (uint32_t)row * ARSTR + (uint32_t)((lane >> 3) & 1) * 16;
    }

    float acc[4][8][4];
#pragma unroll
    for (int mt = 0; mt < 4; ++mt)
#pragma unroll
        for (int nt = 0; nt < 8; ++nt)
#pragma unroll
            for (int q = 0; q < 4; ++q) acc[mt][nt][q] = 0.0f;

    // ---- prologue: stage chunks 0..NSTAGE-2 ----
#pragma unroll
    for (int pc = 0; pc < NSTAGE - 1; ++pc) {
        uint32_t st = sb + OFF_STG + pc * STG_BYTES;
        int k0 = pc << 5;
#pragma unroll
        for (int q = 0; q < 4; ++q) {
            cp_async16(st + a_sts + q * 16, asrc + k0 + q * 8);
            cp_async16(st + b_sts + q * 16, bsrc + k0 + q * 8);
        }
        cp_commit();
    }

    // ---- main loop over 32 K-chunks ----
#pragma unroll 1
    for (int c = 0; c < 32; ++c) {
        int s = c & (NSTAGE - 1);
        cp_wait2();          // chunk c resident
        __syncthreads();

        if (c + NSTAGE - 1 < 32) {
            int cn = c + NSTAGE - 1;
            uint32_t st = sb + OFF_STG + (cn & (NSTAGE - 1)) * STG_BYTES;
            int k0 = cn << 5;
#pragma unroll
            for (int q = 0; q < 4; ++q) {
                cp_async16(st + a_sts + q * 16, asrc + k0 + q * 8);
                cp_async16(st + b_sts + q * 16, bsrc + k0 + q * 8);
            }
        }
        cp_commit();         // commit every iter (possibly empty) to keep group math valid

        uint32_t stage = sb + OFF_STG + s * STG_BYTES;
#pragma unroll
        for (int ks = 0; ks < 2; ++ks) {
            uint32_t a[4][4], b[4][4];
#pragma unroll
            for (int mt = 0; mt < 4; ++mt)
                ldsm_x4(a[mt][0], a[mt][1], a[mt][2], a[mt][3],
                        stage + a_off[mt] + ks * 32);
#pragma unroll
            for (int g = 0; g < 4; ++g)
                ldsm_x4(b[g][0], b[g][1], b[g][2], b[g][3],
                        stage + b_off[g] + ks * 32);
#pragma unroll
            for (int mt = 0; mt < 4; ++mt) {
#pragma unroll
                for (int g = 0; g < 4; ++g) {
                    mma_fp16(acc[mt][g * 2][0], acc[mt][g * 2][1],
                             acc[mt][g * 2][2], acc[mt][g * 2][3],
                             a[mt][0], a[mt][1], a[mt][2], a[mt][3],
                             b[g][0], b[g][1]);
                    mma_fp16(acc[mt][g * 2 + 1][0], acc[mt][g * 2 + 1][1],
                             acc[mt][g * 2 + 1][2], acc[mt][g * 2 + 1][3],
                             a[mt][0], a[mt][1], a[mt][2], a[mt][3],
                             b[g][2], b[g][3]);
                }
            }
        }
    }

    // ---- epilogue: bias + store ----
    int gr = lane >> 2, gc2 = (lane & 3) * 2;
    const float* bias_w = bias_s + wn * 64;
#pragma unroll
    for (int mt = 0; mt < 4; ++mt) {
#pragma unroll
        for (int half = 0; half < 2; ++half) {
            int row = m0 + wm * 64 + mt * 16 + gr + half * 8;
            float* orow = out + (size_t)row * Vdim + n0 + wn * 64;
#pragma unroll
            for (int nt = 0; nt < 8; ++nt) {
                int col = nt * 8 + gc2;
                float2 v;
                v.x = acc[mt][nt][half * 2 + 0] + bias_w[col];
                v.y = acc[mt][nt][half * 2 + 1] + bias_w[col + 1];
                *(float2*)(orow + col) = v;
            }
        }
    }
}

// ================= launch =================
extern "C" void kernel_launch(void* const* d_in, const int* in_sizes, int n_in,
                              void* d_out, int out_size) {
    const float* enc    = (const float*)d_in[0];
    const float* pred   = (const float*)d_in[1];
    const float* W_enc  = (const float*)d_in[2];
    const float* b_enc  = (const float*)d_in[3];
    const float* W_pred = (const float*)d_in[4];
    const float* b_pred = (const float*)d_in[5];
    const float* W_out  = (const float*)d_in[6];
    const float* b_out  = (const float*)d_in[7];
    float* out = (float*)d_out;

    cudaFuncSetAttribute(gemm_kernel,
                         cudaFuncAttributeMaxDynamicSharedMemorySize, GEMM_SMEM);

    // enc_out = enc @ W_enc + b_enc : M = B*T = 1024
    proj_kernel<<<dim3(Jdim / 64, 1024 / 64), 256>>>(enc, W_enc, b_enc, 0);
    // pred_out = pred @ W_pred + b_pred : M = B*U = 256
    proj_kernel<<<dim3(Jdim / 64, 256 / 64), 256>>>(pred, W_pred, b_pred, 1);
    // Wt fp16 = W_out^T
    transpose_h_kernel<<<dim3(Vdim / 32, Jdim / 32), 256>>>(W_out);
    // A_h = fp16(tanh(enc_out (+) pred_out))  [65536, 1024]
    tanh_pre_kernel<<<32768, 256>>>();
    // pure fp16 GEMM: CTA 128x128, grid (N-tiles fast, M-tiles)
    gemm_kernel<<<dim3(8, 512), 128, GEMM_SMEM>>>(b_out, out);
}

// round 7
// speedup vs baseline: 1.2290x; 1.2290x over previous
#include <cuda_runtime.h>
#include <cuda_fp16.h>
#include <cstdint>
#include <cstddef>

#define DEVINL __device__ __forceinline__

// ---------------- problem dims ----------------
constexpr int Bdim = 4, Tdim = 256, Udim = 64, Ddim = 512, Jdim = 1024, Vdim = 1024;
constexpr int Mtot = Bdim * Tdim * Udim;  // 65536

// ---------------- device scratch (allocs forbidden) ----------------
__device__ float g_enc_out[Bdim * Tdim * Jdim];   // 4 MB  [1024, 1024]
__device__ float g_pred_out[Bdim * Udim * Jdim];  // 1 MB  [256, 1024]
__device__ __half g_Wth[Vdim * Jdim];             // 2 MB  W_out^T, fp16
__device__ __half g_Ah[(size_t)Mtot * Jdim];      // 134 MB  tanh(joint), fp16

// ---------------- PTX helpers (baseline ISA, sm_80-level) ----------------
DEVINL uint32_t smem_u32(const void* p) {
    uint32_t a;
    asm("{ .reg .u64 t; cvta.to.shared.u64 t, %1; cvt.u32.u64 %0, t; }" : "=r"(a) : "l"(p));
    return a;
}
DEVINL void cp_async16(uint32_t dst, const void* src) {
    asm volatile("cp.async.cg.shared.global [%0], [%1], 16;" :: "r"(dst), "l"(src) : "memory");
}
DEVINL void cp_commit() { asm volatile("cp.async.commit_group;" ::: "memory"); }
DEVINL void cp_wait2() { asm volatile("cp.async.wait_group 2;" ::: "memory"); }

DEVINL void ldsm_x4(uint32_t& r0, uint32_t& r1, uint32_t& r2, uint32_t& r3, uint32_t addr) {
    asm volatile("ldmatrix.sync.aligned.m8n8.x4.shared.b16 {%0,%1,%2,%3}, [%4];"
                 : "=r"(r0), "=r"(r1), "=r"(r2), "=r"(r3) : "r"(addr));
}
DEVINL void mma_fp16(float& c0, float& c1, float& c2, float& c3,
                     uint32_t a0, uint32_t a1, uint32_t a2, uint32_t a3,
                     uint32_t b0, uint32_t b1) {
    asm volatile(
        "mma.sync.aligned.m16n8k16.row.col.f32.f16.f16.f32 "
        "{%0,%1,%2,%3}, {%4,%5,%6,%7}, {%8,%9}, {%0,%1,%2,%3};"
        : "+f"(c0), "+f"(c1), "+f"(c2), "+f"(c3)
        : "r"(a0), "r"(a1), "r"(a2), "r"(a3), "r"(b0), "r"(b1));
}

// accurate tanh (ex2.approx + rcp.approx, ~1e-6 rel)
DEVINL float tanh_fast(float x) {
    x = fminf(20.0f, fmaxf(-20.0f, x));
    float e;
    asm("ex2.approx.f32 %0, %1;" : "=f"(e) : "f"(x * 2.885390081777927f)); // 2*log2(e)
    float r;
    asm("rcp.approx.f32 %0, %1;" : "=f"(r) : "f"(e + 1.0f));
    return (e - 1.0f) * r;
}
DEVINL uint32_t pack_h2(float lo, float hi) {
    __half2 h = __floats2half2_rn(lo, hi);
    return *(uint32_t*)&h;
}

// ================= kernel 1: fp32 projection GEMM (C = X @ W + bias) =================
__global__ __launch_bounds__(256) void proj_kernel(const float* __restrict__ X,
                                                   const float* __restrict__ W,
                                                   const float* __restrict__ bias,
                                                   int which) {
    float* __restrict__ C = which ? g_pred_out : g_enc_out;
    __shared__ float As[16][68];
    __shared__ float Bs[16][64];
    int tid = threadIdx.x;
    int m0 = blockIdx.y * 64;
    int n0 = blockIdx.x * 64;
    int ty = tid >> 4, tx = tid & 15;
    int a_m = tid >> 2, a_kq = tid & 3;
    int b_k = tid >> 4, b_nq = tid & 15;

    float acc[4][4];
#pragma unroll
    for (int i = 0; i < 4; ++i)
#pragma unroll
        for (int j = 0; j < 4; ++j) acc[i][j] = 0.0f;

    for (int k0 = 0; k0 < Ddim; k0 += 16) {
        float4 av = *(const float4*)(X + (size_t)(m0 + a_m) * Ddim + k0 + a_kq * 4);
        float4 bv = *(const float4*)(W + (size_t)(k0 + b_k) * Jdim + n0 + b_nq * 4);
        __syncthreads();
        As[a_kq * 4 + 0][a_m] = av.x;
        As[a_kq * 4 + 1][a_m] = av.y;
        As[a_kq * 4 + 2][a_m] = av.z;
        As[a_kq * 4 + 3][a_m] = av.w;
        *(float4*)&Bs[b_k][b_nq * 4] = bv;
        __syncthreads();
#pragma unroll
        for (int kk = 0; kk < 16; ++kk) {
            float a[4], b[4];
#pragma unroll
            for (int i = 0; i < 4; ++i) a[i] = As[kk][ty * 4 + i];
            float4 b4 = *(const float4*)&Bs[kk][tx * 4];
            b[0] = b4.x; b[1] = b4.y; b[2] = b4.z; b[3] = b4.w;
#pragma unroll
            for (int i = 0; i < 4; ++i)
#pragma unroll
                for (int j = 0; j < 4; ++j) acc[i][j] = fmaf(a[i], b[j], acc[i][j]);
        }
    }
#pragma unroll
    for (int i = 0; i < 4; ++i) {
#pragma unroll
        for (int j = 0; j < 4; ++j) {
            int n = n0 + tx * 4 + j;
            C[(size_t)(m0 + ty * 4 + i) * Jdim + n] = acc[i][j] + bias[n];
        }
    }
}

// ======== kernel 2: transpose W_out [J,V] -> g_Wth [V,J] in fp16 ========
__global__ __launch_bounds__(256) void transpose_h_kernel(const float* __restrict__ W) {
    __shared__ float tile[32][33];
    int v0 = blockIdx.x * 32;
    int j0 = blockIdx.y * 32;
    int tx = threadIdx.x & 31;
    int ty = threadIdx.x >> 5;  // 0..7
#pragma unroll
    for (int i = 0; i < 32; i += 8)
        tile[ty + i][tx] = W[(size_t)(j0 + ty + i) * Vdim + v0 + tx];
    __syncthreads();
#pragma unroll
    for (int i = 0; i < 32; i += 8)
        g_Wth[(size_t)(v0 + ty + i) * Jdim + j0 + tx] = __float2half_rn(tile[tx][ty + i]);
}

// ======== kernel 3: A_h[m][k] = fp16(tanh(enc_out[b,t,k] + pred_out[b,u,k])) ========
// one block = one m row (128 threads x 8 k each). 65536 blocks.
__global__ __launch_bounds__(128) void tanh_pre_kernel() {
    int m = blockIdx.x;
    int b = m >> 14, t = (m >> 6) & (Tdim - 1), u = m & (Udim - 1);
    int kc = threadIdx.x * 8;
    const float* e = g_enc_out + ((size_t)((b << 8) + t) << 10) + kc;
    const float* p = g_pred_out + ((size_t)((b << 6) + u) << 10) + kc;
    float4 e0 = *(const float4*)e;
    float4 p0 = *(const float4*)p;
    float4 e1 = *(const float4*)(e + 4);
    float4 p1 = *(const float4*)(p + 4);
    uint4 o;
    o.x = pack_h2(tanh_fast(e0.x + p0.x), tanh_fast(e0.y + p0.y));
    o.y = pack_h2(tanh_fast(e0.z + p0.z), tanh_fast(e0.w + p0.w));
    o.z = pack_h2(tanh_fast(e1.x + p1.x), tanh_fast(e1.y + p1.y));
    o.w = pack_h2(tanh_fast(e1.z + p1.z), tanh_fast(e1.w + p1.w));
    *(uint4*)(g_Ah + ((size_t)m << 10) + kc) = o;
}

// ================= kernel 4: pure fp16 GEMM  out = A_h @ Wt^T + bias =================
// CTA tile 128(M) x 256(N), 512 threads = 16 warps (4M x 4N), warp tile 32x64.
// 4-stage cp.async(.cg) pipeline.
constexpr int ARSTR = 80;                        // bytes per smem row (64B data + pad)
constexpr int ABYTES = 128 * ARSTR;              // 10240
constexpr int BBYTES = 256 * ARSTR;              // 20480
constexpr int STG_BYTES = ABYTES + BBYTES;       // 30720
constexpr int NSTAGE = 4;
constexpr int OFF_STG = 1024;
constexpr int GEMM_SMEM = OFF_STG + NSTAGE * STG_BYTES;  // 123904

__global__ __launch_bounds__(512, 1) void gemm_kernel(
    const float* __restrict__ b_out, float* __restrict__ out) {
    extern __shared__ char smem[];
    uint32_t sb = smem_u32(smem);
    float* bias_s = (float*)smem;

    int tid = threadIdx.x;
    int lane = tid & 31;
    int wid = tid >> 5;       // 0..15
    int wm = wid >> 2;        // 0..3  (32-row slab)
    int wn = wid & 3;         // 0..3  (64-col slab)

    int n0 = blockIdx.x << 8;          // N-tile (fast dim -> A reuse in L2)
    int m0 = blockIdx.y << 7;          // M-tile

    if (tid < 256) bias_s[tid] = b_out[n0 + tid];

    // ---- producer addressing ----
    // A: 512 granules of 16B per chunk, 1 per thread
    int arow = tid >> 2, aq = tid & 3;
    const __half* asrc = g_Ah + ((size_t)(m0 + arow) << 10) + aq * 8;
    uint32_t a_sts = (uint32_t)arow * ARSTR + aq * 16;
    // B: 1024 granules per chunk, 2 per thread (rows r, r+128)
    const __half* bsrc = g_Wth + ((size_t)(n0 + arow) << 10) + aq * 8;
    uint32_t b_sts = ABYTES + (uint32_t)arow * ARSTR + aq * 16;

    // ---- consumer LDSM per-lane offsets ----
    uint32_t a_off[2], b_off[4];
#pragma unroll
    for (int mt = 0; mt < 2; ++mt) {
        int row = wm * 32 + mt * 16 + (lane & 15);
        a_off[mt] = (uint32_t)row * ARSTR + (uint32_t)(lane >> 4) * 16;
    }
#pragma unroll
    for (int g = 0; g < 4; ++g) {
        int row = wn * 64 + g * 16 + (lane & 7) + ((lane >> 4) & 1) * 8;
        b_off[g] = ABYTES + (uint32_t)row * ARSTR + (uint32_t)((lane >> 3) & 1) * 16;
    }

    float acc[2][8][4];
#pragma unroll
    for (int mt = 0; mt < 2; ++mt)
#pragma unroll
        for (int nt = 0; nt < 8; ++nt)
#pragma unroll
            for (int q = 0; q < 4; ++q) acc[mt][nt][q] = 0.0f;

    // ---- prologue: stage chunks 0..NSTAGE-2 ----
#pragma unroll
    for (int pc = 0; pc < NSTAGE - 1; ++pc) {
        uint32_t st = sb + OFF_STG + pc * STG_BYTES;
        int k0 = pc << 5;
        cp_async16(st + a_sts, asrc + k0);
        cp_async16(st + b_sts, bsrc + k0);
        cp_async16(st + b_sts + 128 * ARSTR, bsrc + k0 + (size_t)128 * Jdim);
        cp_commit();
    }

    // ---- main loop over 32 K-chunks ----
#pragma unroll 1
    for (int c = 0; c < 32; ++c) {
        int s = c & (NSTAGE - 1);
        cp_wait2();          // chunk c resident
        __syncthreads();

        if (c + NSTAGE - 1 < 32) {
            int cn = c + NSTAGE - 1;
            uint32_t st = sb + OFF_STG + (cn & (NSTAGE - 1)) * STG_BYTES;
            int k0 = cn << 5;
            cp_async16(st + a_sts, asrc + k0);
            cp_async16(st + b_sts, bsrc + k0);
            cp_async16(st + b_sts + 128 * ARSTR, bsrc + k0 + (size_t)128 * Jdim);
        }
        cp_commit();         // commit every iter (possibly empty) to keep group math valid

        uint32_t stage = sb + OFF_STG + s * STG_BYTES;
#pragma unroll
        for (int ks = 0; ks < 2; ++ks) {
            uint32_t a[2][4], b[4][4];
#pragma unroll
            for (int mt = 0; mt < 2; ++mt)
                ldsm_x4(a[mt][0], a[mt][1], a[mt][2], a[mt][3],
                        stage + a_off[mt] + ks * 32);
#pragma unroll
            for (int g = 0; g < 4; ++g)
                ldsm_x4(b[g][0], b[g][1], b[g][2], b[g][3],
                        stage + b_off[g] + ks * 32);
#pragma unroll
            for (int mt = 0; mt < 2; ++mt) {
#pragma unroll
                for (int g = 0; g < 4; ++g) {
                    mma_fp16(acc[mt][g * 2][0], acc[mt][g * 2][1],
                             acc[mt][g * 2][2], acc[mt][g * 2][3],
                             a[mt][0], a[mt][1], a[mt][2], a[mt][3],
                             b[g][0], b[g][1]);
                    mma_fp16(acc[mt][g * 2 + 1][0], acc[mt][g * 2 + 1][1],
                             acc[mt][g * 2 + 1][2], acc[mt][g * 2 + 1][3],
                             a[mt][0], a[mt][1], a[mt][2], a[mt][3],
                             b[g][2], b[g][3]);
                }
            }
        }
    }

    // ---- epilogue: bias + store ----
    int gr = lane >> 2, gc2 = (lane & 3) * 2;
    const float* bias_w = bias_s + wn * 64;
#pragma unroll
    for (int mt = 0; mt < 2; ++mt) {
#pragma unroll
        for (int half = 0; half < 2; ++half) {
            int row = m0 + wm * 32 + mt * 16 + gr + half * 8;
            float* orow = out + (size_t)row * Vdim + n0 + wn * 64;
#pragma unroll
            for (int nt = 0; nt < 8; ++nt) {
                int col = nt * 8 + gc2;
                float2 v;
                v.x = acc[mt][nt][half * 2 + 0] + bias_w[col];
                v.y = acc[mt][nt][half * 2 + 1] + bias_w[col + 1];
                *(float2*)(orow + col) = v;
            }
        }
    }
}

// ================= launch =================
extern "C" void kernel_launch(void* const* d_in, const int* in_sizes, int n_in,
                              void* d_out, int out_size) {
    const float* enc    = (const float*)d_in[0];
    const float* pred   = (const float*)d_in[1];
    const float* W_enc  = (const float*)d_in[2];
    const float* b_enc  = (const float*)d_in[3];
    const float* W_pred = (const float*)d_in[4];
    const float* b_pred = (const float*)d_in[5];
    const float* W_out  = (const float*)d_in[6];
    const float* b_out  = (const float*)d_in[7];
    float* out = (float*)d_out;

    cudaFuncSetAttribute(gemm_kernel,
                         cudaFuncAttributeMaxDynamicSharedMemorySize, GEMM_SMEM);

    // enc_out = enc @ W_enc + b_enc : M = B*T = 1024
    proj_kernel<<<dim3(Jdim / 64, 1024 / 64), 256>>>(enc, W_enc, b_enc, 0);
    // pred_out = pred @ W_pred + b_pred : M = B*U = 256
    proj_kernel<<<dim3(Jdim / 64, 256 / 64), 256>>>(pred, W_pred, b_pred, 1);
    // Wt fp16 = W_out^T
    transpose_h_kernel<<<dim3(Vdim / 32, Jdim / 32), 256>>>(W_out);
    // A_h = fp16(tanh(enc_out (+) pred_out))  [65536, 1024]
    tanh_pre_kernel<<<Mtot, 128>>>();
    // pure fp16 GEMM: CTA 128x256, 512 threads, grid (N-tiles fast, M-tiles)
    gemm_kernel<<<dim3(4, 512), 512, GEMM_SMEM>>>(b_out, out);
}

// round 8
// speedup vs baseline: 1.4799x; 1.2041x over previous
#include <cuda_runtime.h>
#include <cuda_fp16.h>
#include <cstdint>
#include <cstddef>

#define DEVINL __device__ __forceinline__

// ---------------- problem dims ----------------
constexpr int Bdim = 4, Tdim = 256, Udim = 64, Ddim = 512, Jdim = 1024, Vdim = 1024;
constexpr int Mtot = Bdim * Tdim * Udim;  // 65536
constexpr int NMT = Mtot / 16;            // 4096 m-tiles
constexpr int NKT = Jdim / 16;            // 64 k-tiles
constexpr int NNT = Vdim / 16;            // 64 n-tiles

// ---------------- device scratch (allocs forbidden) ----------------
__device__ float g_enc_out[Bdim * Tdim * Jdim];   // 4 MB
__device__ float g_pred_out[Bdim * Udim * Jdim];  // 1 MB
// fragment-packed operands: tile (16x16 fp16) = 32 lanes x uint4
__device__ uint4 g_Aft[(size_t)NMT * NKT * 32];   // 134 MB
__device__ uint4 g_Bft[(size_t)NNT * NKT * 32];   // 2 MB

// ---------------- PTX helpers ----------------
DEVINL void mma_fp16(float& c0, float& c1, float& c2, float& c3,
                     uint32_t a0, uint32_t a1, uint32_t a2, uint32_t a3,
                     uint32_t b0, uint32_t b1) {
    asm volatile(
        "mma.sync.aligned.m16n8k16.row.col.f32.f16.f16.f32 "
        "{%0,%1,%2,%3}, {%4,%5,%6,%7}, {%8,%9}, {%0,%1,%2,%3};"
        : "+f"(c0), "+f"(c1), "+f"(c2), "+f"(c3)
        : "r"(a0), "r"(a1), "r"(a2), "r"(a3), "r"(b0), "r"(b1));
}

// accurate tanh (ex2.approx + rcp.approx, ~1e-6 rel)
DEVINL float tanh_fast(float x) {
    x = fminf(20.0f, fmaxf(-20.0f, x));
    float e;
    asm("ex2.approx.f32 %0, %1;" : "=f"(e) : "f"(x * 2.885390081777927f)); // 2*log2(e)
    float r;
    asm("rcp.approx.f32 %0, %1;" : "=f"(r) : "f"(e + 1.0f));
    return (e - 1.0f) * r;
}
DEVINL uint32_t pack_h2(float lo, float hi) {
    __half2 h = __floats2half2_rn(lo, hi);
    return *(uint32_t*)&h;
}

// ================= kernel 1: fp32 projection GEMM (C = X @ W + bias) =================
__global__ __launch_bounds__(256) void proj_kernel(const float* __restrict__ X,
                                                   const float* __restrict__ W,
                                                   const float* __restrict__ bias,
                                                   int which) {
    float* __restrict__ C = which ? g_pred_out : g_enc_out;
    __shared__ float As[16][68];
    __shared__ float Bs[16][64];
    int tid = threadIdx.x;
    int m0 = blockIdx.y * 64;
    int n0 = blockIdx.x * 64;
    int ty = tid >> 4, tx = tid & 15;
    int a_m = tid >> 2, a_kq = tid & 3;
    int b_k = tid >> 4, b_nq = tid & 15;

    float acc[4][4];
#pragma unroll
    for (int i = 0; i < 4; ++i)
#pragma unroll
        for (int j = 0; j < 4; ++j) acc[i][j] = 0.0f;

    for (int k0 = 0; k0 < Ddim; k0 += 16) {
        float4 av = *(const float4*)(X + (size_t)(m0 + a_m) * Ddim + k0 + a_kq * 4);
        float4 bv = *(const float4*)(W + (size_t)(k0 + b_k) * Jdim + n0 + b_nq * 4);
        __syncthreads();
        As[a_kq * 4 + 0][a_m] = av.x;
        As[a_kq * 4 + 1][a_m] = av.y;
        As[a_kq * 4 + 2][a_m] = av.z;
        As[a_kq * 4 + 3][a_m] = av.w;
        *(float4*)&Bs[b_k][b_nq * 4] = bv;
        __syncthreads();
#pragma unroll
        for (int kk = 0; kk < 16; ++kk) {
            float a[4], b[4];
#pragma unroll
            for (int i = 0; i < 4; ++i) a[i] = As[kk][ty * 4 + i];
            float4 b4 = *(const float4*)&Bs[kk][tx * 4];
            b[0] = b4.x; b[1] = b4.y; b[2] = b4.z; b[3] = b4.w;
#pragma unroll
            for (int i = 0; i < 4; ++i)
#pragma unroll
                for (int j = 0; j < 4; ++j) acc[i][j] = fmaf(a[i], b[j], acc[i][j]);
        }
    }
#pragma unroll
    for (int i = 0; i < 4; ++i) {
#pragma unroll
        for (int j = 0; j < 4; ++j) {
            int n = n0 + tx * 4 + j;
            C[(size_t)(m0 + ty * 4 + i) * Jdim + n] = acc[i][j] + bias[n];
        }
    }
}

// ======== kernel 2: pack W_out [J(k),V(n)] into fragment tiles g_Bft ========
// tile (nt, kt): lane l holds b0,b1 (cols n_lo) and b0,b1 (cols n_lo+8)
__global__ __launch_bounds__(128) void wpack_kernel(const float* __restrict__ W) {
    int tile = blockIdx.x * 4 + (threadIdx.x >> 5);  // 0..4095 = nt*64 + kt
    int nt = tile >> 6, kt = tile & 63;
    int lane = threadIdx.x & 31;
    int c = lane >> 2, kc = (lane & 3) * 2;
    int k0 = kt * 16 + kc;
    int n_lo = nt * 16 + c, n_hi = n_lo + 8;
    uint4 o;
    o.x = pack_h2(W[(size_t)k0 * Vdim + n_lo],       W[(size_t)(k0 + 1) * Vdim + n_lo]);
    o.y = pack_h2(W[(size_t)(k0 + 8) * Vdim + n_lo], W[(size_t)(k0 + 9) * Vdim + n_lo]);
    o.z = pack_h2(W[(size_t)k0 * Vdim + n_hi],       W[(size_t)(k0 + 1) * Vdim + n_hi]);
    o.w = pack_h2(W[(size_t)(k0 + 8) * Vdim + n_hi], W[(size_t)(k0 + 9) * Vdim + n_hi]);
    g_Bft[(size_t)tile * 32 + lane] = o;
}

// ======== kernel 3: tanh(enc+pred) -> fragment tiles g_Aft ========
// block = one m-tile (16 rows). 4 warps; warp w does kt = w, w+4, ...
__global__ __launch_bounds__(128) void tanh_frag_kernel() {
    int mt = blockIdx.x;               // 0..4095
    int lane = threadIdx.x & 31;
    int w = threadIdx.x >> 5;          // 0..3
    int gr = lane >> 2, kc = (lane & 3) * 2;
    int r0 = mt * 16 + gr;             // rows r0, r0+8 share (b,t); u differs by 8
    // enc row: index m>>6 (same for all 16 rows of the tile)
    const float* e = g_enc_out + ((size_t)(r0 >> 6) << 10);
    const float* p0 = g_pred_out + ((size_t)(((r0 >> 14) << 6) + (r0 & 63)) << 10);
    const float* p1 = p0 + ((size_t)8 << 10);   // u+8
    uint4* dst = g_Aft + (size_t)mt * (NKT * 32) + lane;
#pragma unroll 4
    for (int kt = w; kt < NKT; kt += 4) {
        int k0 = kt * 16 + kc;
        float2 eA = *(const float2*)(e + k0);
        float2 eB = *(const float2*)(e + k0 + 8);
        float2 pA0 = *(const float2*)(p0 + k0);
        float2 pB0 = *(const float2*)(p0 + k0 + 8);
        float2 pA1 = *(const float2*)(p1 + k0);
        float2 pB1 = *(const float2*)(p1 + k0 + 8);
        uint4 o;
        o.x = pack_h2(tanh_fast(eA.x + pA0.x), tanh_fast(eA.y + pA0.y));  // a0: (gr,   k0..k0+1)
        o.y = pack_h2(tanh_fast(eA.x + pA1.x), tanh_fast(eA.y + pA1.y));  // a1: (gr+8, k0..k0+1)
        o.z = pack_h2(tanh_fast(eB.x + pB0.x), tanh_fast(eB.y + pB0.y));  // a2: (gr,   k0+8..9)
        o.w = pack_h2(tanh_fast(eB.x + pB1.x), tanh_fast(eB.y + pB1.y));  // a3: (gr+8, k0+8..9)
        dst[kt * 32] = o;
    }
}

// ================= kernel 4: smem-free fp16 GEMM  out = A @ W + bias =================
// CTA 128(M) x 256(N), 256 threads = 8 warps (2M x 4N), warp tile 64x64.
// Operands arrive as mma fragments via LDG.128; register double-buffered; no barriers.
__global__ __launch_bounds__(256, 1) void gemm_kernel(
    const float* __restrict__ b_out, float* __restrict__ out) {
    __shared__ float bias_s[256];

    int tid = threadIdx.x;
    int lane = tid & 31;
    int wid = tid >> 5;
    int wm = wid >> 2;        // 0..1
    int wn = wid & 3;         // 0..3

    int n0 = blockIdx.x << 8;          // N-tile (fast dim -> A reuse in L2)
    int m0 = blockIdx.y << 7;          // M-tile

    bias_s[tid] = b_out[n0 + tid];
    __syncthreads();

    int mt_base = (m0 >> 4) + wm * 4;
    int nt_base = (n0 >> 4) + wn * 4;
    const uint4* aP[4];
    const uint4* bP[4];
#pragma unroll
    for (int i = 0; i < 4; ++i)
        aP[i] = g_Aft + ((size_t)(mt_base + i) << 11) + lane;   // * (64 tiles * 32 lanes)
#pragma unroll
    for (int g = 0; g < 4; ++g)
        bP[g] = g_Bft + ((size_t)(nt_base + g) << 11) + lane;

    float acc[4][8][4];
#pragma unroll
    for (int mt = 0; mt < 4; ++mt)
#pragma unroll
        for (int nt = 0; nt < 8; ++nt)
#pragma unroll
            for (int q = 0; q < 4; ++q) acc[mt][nt][q] = 0.0f;

    uint4 A0[4][2], B0[4][2], A1[4][2], B1[4][2];

#define LOADC(c, Ab, Bb)                                   \
    do {                                                   \
        int _o = (c) * 64;                                 \
        _Pragma("unroll")                                  \
        for (int i = 0; i < 4; ++i) {                      \
            Ab[i][0] = aP[i][_o];                          \
            Ab[i][1] = aP[i][_o + 32];                     \
        }                                                  \
        _Pragma("unroll")                                  \
        for (int g = 0; g < 4; ++g) {                      \
            Bb[g][0] = bP[g][_o];                          \
            Bb[g][1] = bP[g][_o + 32];                     \
        }                                                  \
    } while (0)

#define COMPUTE(Ab, Bb)                                                         \
    do {                                                                        \
        _Pragma("unroll")                                                       \
        for (int ks = 0; ks < 2; ++ks) {                                        \
            _Pragma("unroll")                                                   \
            for (int i = 0; i < 4; ++i) {                                       \
                _Pragma("unroll")                                               \
                for (int g = 0; g < 4; ++g) {                                   \
                    mma_fp16(acc[i][g * 2][0], acc[i][g * 2][1],                \
                             acc[i][g * 2][2], acc[i][g * 2][3],                \
                             Ab[i][ks].x, Ab[i][ks].y, Ab[i][ks].z, Ab[i][ks].w,\
                             Bb[g][ks].x, Bb[g][ks].y);                         \
                    mma_fp16(acc[i][g * 2 + 1][0], acc[i][g * 2 + 1][1],        \
                             acc[i][g * 2 + 1][2], acc[i][g * 2 + 1][3],        \
                             Ab[i][ks].x, Ab[i][ks].y, Ab[i][ks].z, Ab[i][ks].w,\
                             Bb[g][ks].z, Bb[g][ks].w);                         \
                }                                                               \
            }                                                                   \
        }                                                                       \
    } while (0)

    LOADC(0, A0, B0);
#pragma unroll 1
    for (int c = 0; c < 32; c += 2) {
        if (c + 1 < 32) LOADC(c + 1, A1, B1);
        COMPUTE(A0, B0);
        if (c + 2 < 32) LOADC(c + 2, A0, B0);
        COMPUTE(A1, B1);
    }
#undef LOADC
#undef COMPUTE

    // ---- epilogue: bias + store ----
    int gr = lane >> 2, gc2 = (lane & 3) * 2;
    const float* bias_w = bias_s + wn * 64;
#pragma unroll
    for (int mt = 0; mt < 4; ++mt) {
#pragma unroll
        for (int half = 0; half < 2; ++half) {
            int row = m0 + wm * 64 + mt * 16 + gr + half * 8;
            float* orow = out + (size_t)row * Vdim + n0 + wn * 64;
#pragma unroll
            for (int nt = 0; nt < 8; ++nt) {
                int col = nt * 8 + gc2;
                float2 v;
                v.x = acc[mt][nt][half * 2 + 0] + bias_w[col];
                v.y = acc[mt][nt][half * 2 + 1] + bias_w[col + 1];
                *(float2*)(orow + col) = v;
            }
        }
    }
}

// ================= launch =================
extern "C" void kernel_launch(void* const* d_in, const int* in_sizes, int n_in,
                              void* d_out, int out_size) {
    const float* enc    = (const float*)d_in[0];
    const float* pred   = (const float*)d_in[1];
    const float* W_enc  = (const float*)d_in[2];
    const float* b_enc  = (const float*)d_in[3];
    const float* W_pred = (const float*)d_in[4];
    const float* b_pred = (const float*)d_in[5];
    const float* W_out  = (const float*)d_in[6];
    const float* b_out  = (const float*)d_in[7];
    float* out = (float*)d_out;

    // enc_out = enc @ W_enc + b_enc : M = B*T = 1024
    proj_kernel<<<dim3(Jdim / 64, 1024 / 64), 256>>>(enc, W_enc, b_enc, 0);
    // pred_out = pred @ W_pred + b_pred : M = B*U = 256
    proj_kernel<<<dim3(Jdim / 64, 256 / 64), 256>>>(pred, W_pred, b_pred, 1);
    // W_out -> fragment tiles
    wpack_kernel<<<(NNT * NKT) / 4, 128>>>(W_out);
    // A = tanh(enc_out (+) pred_out) -> fragment tiles
    tanh_frag_kernel<<<NMT, 128>>>();
    // smem-free fragment GEMM
    gemm_kernel<<<dim3(4, 512), 256>>>(b_out, out);
}

// round 9
// speedup vs baseline: 1.5250x; 1.0305x over previous
#include <cuda_runtime.h>
#include <cuda_fp16.h>
#include <cstdint>
#include <cstddef>

#define DEVINL __device__ __forceinline__

// ---------------- problem dims ----------------
constexpr int Bdim = 4, Tdim = 256, Udim = 64, Ddim = 512, Jdim = 1024, Vdim = 1024;
constexpr int Mtot = Bdim * Tdim * Udim;  // 65536
constexpr int NMT = Mtot / 16;            // 4096 m-tiles
constexpr int NKT = Jdim / 16;            // 64 k-tiles
constexpr int NNT = Vdim / 16;            // 64 n-tiles

// ---------------- device scratch (allocs forbidden) ----------------
__device__ float g_enc_out[Bdim * Tdim * Jdim];   // 4 MB
__device__ float g_pred_out[Bdim * Udim * Jdim];  // 1 MB
// fragment-packed operands: tile (16x16 fp16) = 32 lanes x uint4
__device__ uint4 g_Aft[(size_t)NMT * NKT * 32];   // 134 MB
__device__ uint4 g_Bft[(size_t)NNT * NKT * 32];   // 2 MB

// ---------------- PTX helpers ----------------
DEVINL void mma_fp16(float& c0, float& c1, float& c2, float& c3,
                     uint32_t a0, uint32_t a1, uint32_t a2, uint32_t a3,
                     uint32_t b0, uint32_t b1) {
    asm volatile(
        "mma.sync.aligned.m16n8k16.row.col.f32.f16.f16.f32 "
        "{%0,%1,%2,%3}, {%4,%5,%6,%7}, {%8,%9}, {%0,%1,%2,%3};"
        : "+f"(c0), "+f"(c1), "+f"(c2), "+f"(c3)
        : "r"(a0), "r"(a1), "r"(a2), "r"(a3), "r"(b0), "r"(b1));
}

// accurate tanh (ex2.approx + rcp.approx, ~1e-6 rel)
DEVINL float tanh_fast(float x) {
    x = fminf(20.0f, fmaxf(-20.0f, x));
    float e;
    asm("ex2.approx.f32 %0, %1;" : "=f"(e) : "f"(x * 2.885390081777927f)); // 2*log2(e)
    float r;
    asm("rcp.approx.f32 %0, %1;" : "=f"(r) : "f"(e + 1.0f));
    return (e - 1.0f) * r;
}
DEVINL uint32_t pack_h2(float lo, float hi) {
    __half2 h = __floats2half2_rn(lo, hi);
    return *(uint32_t*)&h;
}

// ================= kernel 1: fp32 projection GEMM (C = X @ W + bias) =================
__global__ __launch_bounds__(256) void proj_kernel(const float* __restrict__ X,
                                                   const float* __restrict__ W,
                                                   const float* __restrict__ bias,
                                                   int which) {
    float* __restrict__ C = which ? g_pred_out : g_enc_out;
    __shared__ float As[16][68];
    __shared__ float Bs[16][64];
    int tid = threadIdx.x;
    int m0 = blockIdx.y * 64;
    int n0 = blockIdx.x * 64;
    int ty = tid >> 4, tx = tid & 15;
    int a_m = tid >> 2, a_kq = tid & 3;
    int b_k = tid >> 4, b_nq = tid & 15;

    float acc[4][4];
#pragma unroll
    for (int i = 0; i < 4; ++i)
#pragma unroll
        for (int j = 0; j < 4; ++j) acc[i][j] = 0.0f;

    for (int k0 = 0; k0 < Ddim; k0 += 16) {
        float4 av = *(const float4*)(X + (size_t)(m0 + a_m) * Ddim + k0 + a_kq * 4);
        float4 bv = *(const float4*)(W + (size_t)(k0 + b_k) * Jdim + n0 + b_nq * 4);
        __syncthreads();
        As[a_kq * 4 + 0][a_m] = av.x;
        As[a_kq * 4 + 1][a_m] = av.y;
        As[a_kq * 4 + 2][a_m] = av.z;
        As[a_kq * 4 + 3][a_m] = av.w;
        *(float4*)&Bs[b_k][b_nq * 4] = bv;
        __syncthreads();
#pragma unroll
        for (int kk = 0; kk < 16; ++kk) {
            float a[4], b[4];
#pragma unroll
            for (int i = 0; i < 4; ++i) a[i] = As[kk][ty * 4 + i];
            float4 b4 = *(const float4*)&Bs[kk][tx * 4];
            b[0] = b4.x; b[1] = b4.y; b[2] = b4.z; b[3] = b4.w;
#pragma unroll
            for (int i = 0; i < 4; ++i)
#pragma unroll
                for (int j = 0; j < 4; ++j) acc[i][j] = fmaf(a[i], b[j], acc[i][j]);
        }
    }
#pragma unroll
    for (int i = 0; i < 4; ++i) {
#pragma unroll
        for (int j = 0; j < 4; ++j) {
            int n = n0 + tx * 4 + j;
            C[(size_t)(m0 + ty * 4 + i) * Jdim + n] = acc[i][j] + bias[n];
        }
    }
}

// ======== kernel 2: pack W_out [J(k),V(n)] into fragment tiles g_Bft ========
__global__ __launch_bounds__(128) void wpack_kernel(const float* __restrict__ W) {
    int tile = blockIdx.x * 4 + (threadIdx.x >> 5);  // 0..4095 = nt*64 + kt
    int nt = tile >> 6, kt = tile & 63;
    int lane = threadIdx.x & 31;
    int c = lane >> 2, kc = (lane & 3) * 2;
    int k0 = kt * 16 + kc;
    int n_lo = nt * 16 + c, n_hi = n_lo + 8;
    uint4 o;
    o.x = pack_h2(W[(size_t)k0 * Vdim + n_lo],       W[(size_t)(k0 + 1) * Vdim + n_lo]);
    o.y = pack_h2(W[(size_t)(k0 + 8) * Vdim + n_lo], W[(size_t)(k0 + 9) * Vdim + n_lo]);
    o.z = pack_h2(W[(size_t)k0 * Vdim + n_hi],       W[(size_t)(k0 + 1) * Vdim + n_hi]);
    o.w = pack_h2(W[(size_t)(k0 + 8) * Vdim + n_hi], W[(size_t)(k0 + 9) * Vdim + n_hi]);
    g_Bft[(size_t)tile * 32 + lane] = o;
}

// ======== kernel 3: tanh(enc+pred) -> fragment tiles g_Aft ========
__global__ __launch_bounds__(128) void tanh_frag_kernel() {
    int mt = blockIdx.x;               // 0..4095
    int lane = threadIdx.x & 31;
    int w = threadIdx.x >> 5;          // 0..3
    int gr = lane >> 2, kc = (lane & 3) * 2;
    int r0 = mt * 16 + gr;             // rows r0, r0+8 share (b,t); u differs by 8
    const float* e = g_enc_out + ((size_t)(r0 >> 6) << 10);
    const float* p0 = g_pred_out + ((size_t)(((r0 >> 14) << 6) + (r0 & 63)) << 10);
    const float* p1 = p0 + ((size_t)8 << 10);   // u+8
    uint4* dst = g_Aft + (size_t)mt * (NKT * 32) + lane;
#pragma unroll 4
    for (int kt = w; kt < NKT; kt += 4) {
        int k0 = kt * 16 + kc;
        float2 eA = *(const float2*)(e + k0);
        float2 eB = *(const float2*)(e + k0 + 8);
        float2 pA0 = *(const float2*)(p0 + k0);
        float2 pB0 = *(const float2*)(p0 + k0 + 8);
        float2 pA1 = *(const float2*)(p1 + k0);
        float2 pB1 = *(const float2*)(p1 + k0 + 8);
        uint4 o;
        o.x = pack_h2(tanh_fast(eA.x + pA0.x), tanh_fast(eA.y + pA0.y));
        o.y = pack_h2(tanh_fast(eA.x + pA1.x), tanh_fast(eA.y + pA1.y));
        o.z = pack_h2(tanh_fast(eB.x + pB0.x), tanh_fast(eB.y + pB0.y));
        o.w = pack_h2(tanh_fast(eB.x + pB1.x), tanh_fast(eB.y + pB1.y));
        dst[kt * 32] = o;
    }
}

// ================= kernel 4: smem-free fp16 GEMM  out = A @ W + bias =================
// CTA 128(M) x 128(N), 128 threads = 4 warps (2M x 2N), warp tile 64x64 (unchanged).
// 2 CTAs resident per SM -> epilogue/prologue/LDG stalls overlap across CTAs.
__global__ __launch_bounds__(128, 2) void gemm_kernel(
    const float* __restrict__ b_out, float* __restrict__ out) {
    __shared__ float bias_s[128];

    int tid = threadIdx.x;
    int lane = tid & 31;
    int wid = tid >> 5;       // 0..3
    int wm = wid >> 1;        // 0..1
    int wn = wid & 1;         // 0..1

    int n0 = blockIdx.x << 7;          // N-tile (fast dim -> A reuse in L2)
    int m0 = blockIdx.y << 7;          // M-tile

    bias_s[tid] = b_out[n0 + tid];
    __syncthreads();

    int mt_base = (m0 >> 4) + wm * 4;
    int nt_base = (n0 >> 4) + wn * 4;
    const uint4* aP[4];
    const uint4* bP[4];
#pragma unroll
    for (int i = 0; i < 4; ++i)
        aP[i] = g_Aft + ((size_t)(mt_base + i) << 11) + lane;   // * (64 tiles * 32 lanes)
#pragma unroll
    for (int g = 0; g < 4; ++g)
        bP[g] = g_Bft + ((size_t)(nt_base + g) << 11) + lane;

    float acc[4][8][4];
#pragma unroll
    for (int mt = 0; mt < 4; ++mt)
#pragma unroll
        for (int nt = 0; nt < 8; ++nt)
#pragma unroll
            for (int q = 0; q < 4; ++q) acc[mt][nt][q] = 0.0f;

    uint4 A0[4][2], B0[4][2], A1[4][2], B1[4][2];

#define LOADC(c, Ab, Bb)                                   \
    do {                                                   \
        int _o = (c) * 64;                                 \
        _Pragma("unroll")                                  \
        for (int i = 0; i < 4; ++i) {                      \
            Ab[i][0] = aP[i][_o];                          \
            Ab[i][1] = aP[i][_o + 32];                     \
        }                                                  \
        _Pragma("unroll")                                  \
        for (int g = 0; g < 4; ++g) {                      \
            Bb[g][0] = bP[g][_o];                          \
            Bb[g][1] = bP[g][_o + 32];                     \
        }                                                  \
    } while (0)

#define COMPUTE(Ab, Bb)                                                         \
    do {                                                                        \
        _Pragma("unroll")                                                       \
        for (int ks = 0; ks < 2; ++ks) {                                        \
            _Pragma("unroll")                                                   \
            for (int i = 0; i < 4; ++i) {                                       \
                _Pragma("unroll")                                               \
                for (int g = 0; g < 4; ++g) {                                   \
                    mma_fp16(acc[i][g * 2][0], acc[i][g * 2][1],                \
                             acc[i][g * 2][2], acc[i][g * 2][3],                \
                             Ab[i][ks].x, Ab[i][ks].y, Ab[i][ks].z, Ab[i][ks].w,\
                             Bb[g][ks].x, Bb[g][ks].y);                         \
                    mma_fp16(acc[i][g * 2 + 1][0], acc[i][g * 2 + 1][1],        \
                             acc[i][g * 2 + 1][2], acc[i][g * 2 + 1][3],        \
                             Ab[i][ks].x, Ab[i][ks].y, Ab[i][ks].z, Ab[i][ks].w,\
                             Bb[g][ks].z, Bb[g][ks].w);                         \
                }                                                               \
            }                                                                   \
        }                                                                       \
    } while (0)

    LOADC(0, A0, B0);
#pragma unroll 1
    for (int c = 0; c < 32; c += 2) {
        if (c + 1 < 32) LOADC(c + 1, A1, B1);
        COMPUTE(A0, B0);
        if (c + 2 < 32) LOADC(c + 2, A0, B0);
        COMPUTE(A1, B1);
    }
#undef LOADC
#undef COMPUTE

    // ---- epilogue: bias + store ----
    int gr = lane >> 2, gc2 = (lane & 3) * 2;
    const float* bias_w = bias_s + wn * 64;
#pragma unroll
    for (int mt = 0; mt < 4; ++mt) {
#pragma unroll
        for (int half = 0; half < 2; ++half) {
            int row = m0 + wm * 64 + mt * 16 + gr + half * 8;
            float* orow = out + (size_t)row * Vdim + n0 + wn * 64;
#pragma unroll
            for (int nt = 0; nt < 8; ++nt) {
                int col = nt * 8 + gc2;
                float2 v;
                v.x = acc[mt][nt][half * 2 + 0] + bias_w[col];
                v.y = acc[mt][nt][half * 2 + 1] + bias_w[col + 1];
                *(float2*)(orow + col) = v;
            }
        }
    }
}

// ================= launch =================
extern "C" void kernel_launch(void* const* d_in, const int* in_sizes, int n_in,
                              void* d_out, int out_size) {
    const float* enc    = (const float*)d_in[0];
    const float* pred   = (const float*)d_in[1];
    const float* W_enc  = (const float*)d_in[2];
    const float* b_enc  = (const float*)d_in[3];
    const float* W_pred = (const float*)d_in[4];
    const float* b_pred = (const float*)d_in[5];
    const float* W_out  = (const float*)d_in[6];
    const float* b_out  = (const float*)d_in[7];
    float* out = (float*)d_out;

    // enc_out = enc @ W_enc + b_enc : M = B*T = 1024
    proj_kernel<<<dim3(Jdim / 64, 1024 / 64), 256>>>(enc, W_enc, b_enc, 0);
    // pred_out = pred @ W_pred + b_pred : M = B*U = 256
    proj_kernel<<<dim3(Jdim / 64, 256 / 64), 256>>>(pred, W_pred, b_pred, 1);
    // W_out -> fragment tiles
    wpack_kernel<<<(NNT * NKT) / 4, 128>>>(W_out);
    // A = tanh(enc_out (+) pred_out) -> fragment tiles
    tanh_frag_kernel<<<NMT, 128>>>();
    // smem-free fragment GEMM: CTA 128x128, 2 CTAs/SM
    gemm_kernel<<<dim3(8, 512), 128>>>(b_out, out);
}

// round 10
// speedup vs baseline: 1.6220x; 1.0637x over previous
#include <cuda_runtime.h>
#include <cuda_fp16.h>
#include <cstdint>
#include <cstddef>

#define DEVINL __device__ __forceinline__

// ---------------- problem dims ----------------
constexpr int Bdim = 4, Tdim = 256, Udim = 64, Ddim = 512, Jdim = 1024, Vdim = 1024;
constexpr int Mtot = Bdim * Tdim * Udim;  // 65536
constexpr int NMT = Mtot / 16;            // 4096 m-tiles
constexpr int NKT = Jdim / 16;            // 64 k-tiles
constexpr int NNT = Vdim / 16;            // 64 n-tiles

// ---------------- device scratch (allocs forbidden) ----------------
__device__ float g_enc_out[Bdim * Tdim * Jdim];   // 4 MB
__device__ float g_pred_out[Bdim * Udim * Jdim];  // 1 MB
// fragment-packed operands: tile (16x16 fp16) = 32 lanes x uint4
__device__ uint4 g_Aft[(size_t)NMT * NKT * 32];   // 134 MB
__device__ uint4 g_Bft[(size_t)NNT * NKT * 32];   // 2 MB

// ---------------- PTX helpers ----------------
DEVINL void mma_fp16(float& c0, float& c1, float& c2, float& c3,
                     uint32_t a0, uint32_t a1, uint32_t a2, uint32_t a3,
                     uint32_t b0, uint32_t b1) {
    asm volatile(
        "mma.sync.aligned.m16n8k16.row.col.f32.f16.f16.f32 "
        "{%0,%1,%2,%3}, {%4,%5,%6,%7}, {%8,%9}, {%0,%1,%2,%3};"
        : "+f"(c0), "+f"(c1), "+f"(c2), "+f"(c3)
        : "r"(a0), "r"(a1), "r"(a2), "r"(a3), "r"(b0), "r"(b1));
}
// non-coherent (read-only, L1-cacheable) 16B load
DEVINL uint4 ldg_nc(const uint4* p) {
    uint4 v;
    asm("ld.global.nc.v4.u32 {%0,%1,%2,%3}, [%4];"
        : "=r"(v.x), "=r"(v.y), "=r"(v.z), "=r"(v.w) : "l"(p));
    return v;
}

// accurate tanh (ex2.approx + rcp.approx, ~1e-6 rel)
DEVINL float tanh_fast(float x) {
    x = fminf(20.0f, fmaxf(-20.0f, x));
    float e;
    asm("ex2.approx.f32 %0, %1;" : "=f"(e) : "f"(x * 2.885390081777927f)); // 2*log2(e)
    float r;
    asm("rcp.approx.f32 %0, %1;" : "=f"(r) : "f"(e + 1.0f));
    return (e - 1.0f) * r;
}
DEVINL uint32_t pack_h2(float lo, float hi) {
    __half2 h = __floats2half2_rn(lo, hi);
    return *(uint32_t*)&h;
}

// ======== kernel 1: merged prep ========
// blocks 0..255   : enc projection   (16 m-tiles x 16 n-tiles of 64x64)
// blocks 256..319 : pred projection  (4 m-tiles x 16 n-tiles)
// blocks 320..351 : W_out fragment pack (128 tiles each)
__device__ DEVINL void proj_tile(const float* __restrict__ X,
                                 const float* __restrict__ W,
                                 const float* __restrict__ bias,
                                 float* __restrict__ C,
                                 int m0, int n0) {
    __shared__ float As[16][68];
    __shared__ float Bs[16][64];
    int tid = threadIdx.x;
    int ty = tid >> 4, tx = tid & 15;
    int a_m = tid >> 2, a_kq = tid & 3;
    int b_k = tid >> 4, b_nq = tid & 15;

    float acc[4][4];
#pragma unroll
    for (int i = 0; i < 4; ++i)
#pragma unroll
        for (int j = 0; j < 4; ++j) acc[i][j] = 0.0f;

    for (int k0 = 0; k0 < Ddim; k0 += 16) {
        float4 av = *(const float4*)(X + (size_t)(m0 + a_m) * Ddim + k0 + a_kq * 4);
        float4 bv = *(const float4*)(W + (size_t)(k0 + b_k) * Jdim + n0 + b_nq * 4);
        __syncthreads();
        As[a_kq * 4 + 0][a_m] = av.x;
        As[a_kq * 4 + 1][a_m] = av.y;
        As[a_kq * 4 + 2][a_m] = av.z;
        As[a_kq * 4 + 3][a_m] = av.w;
        *(float4*)&Bs[b_k][b_nq * 4] = bv;
        __syncthreads();
#pragma unroll
        for (int kk = 0; kk < 16; ++kk) {
            float a[4], b[4];
#pragma unroll
            for (int i = 0; i < 4; ++i) a[i] = As[kk][ty * 4 + i];
            float4 b4 = *(const float4*)&Bs[kk][tx * 4];
            b[0] = b4.x; b[1] = b4.y; b[2] = b4.z; b[3] = b4.w;
#pragma unroll
            for (int i = 0; i < 4; ++i)
#pragma unroll
                for (int j = 0; j < 4; ++j) acc[i][j] = fmaf(a[i], b[j], acc[i][j]);
        }
    }
#pragma unroll
    for (int i = 0; i < 4; ++i) {
#pragma unroll
        for (int j = 0; j < 4; ++j) {
            int n = n0 + tx * 4 + j;
            C[(size_t)(m0 + ty * 4 + i) * Jdim + n] = acc[i][j] + bias[n];
        }
    }
}

__global__ __launch_bounds__(256) void prep_kernel(
    const float* __restrict__ enc, const float* __restrict__ W_enc,
    const float* __restrict__ b_enc,
    const float* __restrict__ pred, const float* __restrict__ W_pred,
    const float* __restrict__ b_pred,
    const float* __restrict__ W_out) {
    int bid = blockIdx.x;
    if (bid < 256) {
        proj_tile(enc, W_enc, b_enc, g_enc_out, (bid >> 4) * 64, (bid & 15) * 64);
    } else if (bid < 320) {
        int lb = bid - 256;
        proj_tile(pred, W_pred, b_pred, g_pred_out, (lb >> 4) * 64, (lb & 15) * 64);
    } else {
        // wpack: 32 CTAs x 128 tiles (8 warps -> 8 tiles per pass, 16 passes)
        int lane = threadIdx.x & 31;
        int w = threadIdx.x >> 5;
        int c = lane >> 2, kc = (lane & 3) * 2;
        int base = (bid - 320) * 128;
#pragma unroll 4
        for (int i = 0; i < 16; ++i) {
            int tile = base + i * 8 + w;          // 0..4095 = nt*64 + kt
            int nt = tile >> 6, kt = tile & 63;
            int k0 = kt * 16 + kc;
            int n_lo = nt * 16 + c, n_hi = n_lo + 8;
            uint4 o;
            o.x = pack_h2(W_out[(size_t)k0 * Vdim + n_lo],       W_out[(size_t)(k0 + 1) * Vdim + n_lo]);
            o.y = pack_h2(W_out[(size_t)(k0 + 8) * Vdim + n_lo], W_out[(size_t)(k0 + 9) * Vdim + n_lo]);
            o.z = pack_h2(W_out[(size_t)k0 * Vdim + n_hi],       W_out[(size_t)(k0 + 1) * Vdim + n_hi]);
            o.w = pack_h2(W_out[(size_t)(k0 + 8) * Vdim + n_hi], W_out[(size_t)(k0 + 9) * Vdim + n_hi]);
            g_Bft[(size_t)tile * 32 + lane] = o;
        }
    }
}

// ======== kernel 2: tanh(enc+pred) -> fragment tiles g_Aft ========
__global__ __launch_bounds__(128) void tanh_frag_kernel() {
    int mt = blockIdx.x;               // 0..4095
    int lane = threadIdx.x & 31;
    int w = threadIdx.x >> 5;          // 0..3
    int gr = lane >> 2, kc = (lane & 3) * 2;
    int r0 = mt * 16 + gr;             // rows r0, r0+8 share (b,t); u differs by 8
    const float* e = g_enc_out + ((size_t)(r0 >> 6) << 10);
    const float* p0 = g_pred_out + ((size_t)(((r0 >> 14) << 6) + (r0 & 63)) << 10);
    const float* p1 = p0 + ((size_t)8 << 10);   // u+8
    uint4* dst = g_Aft + (size_t)mt * (NKT * 32) + lane;
#pragma unroll 4
    for (int kt = w; kt < NKT; kt += 4) {
        int k0 = kt * 16 + kc;
        float2 eA = *(const float2*)(e + k0);
        float2 eB = *(const float2*)(e + k0 + 8);
        float2 pA0 = *(const float2*)(p0 + k0);
        float2 pB0 = *(const float2*)(p0 + k0 + 8);
        float2 pA1 = *(const float2*)(p1 + k0);
        float2 pB1 = *(const float2*)(p1 + k0 + 8);
        uint4 o;
        o.x = pack_h2(tanh_fast(eA.x + pA0.x), tanh_fast(eA.y + pA0.y));
        o.y = pack_h2(tanh_fast(eA.x + pA1.x), tanh_fast(eA.y + pA1.y));
        o.z = pack_h2(tanh_fast(eB.x + pB0.x), tanh_fast(eB.y + pB0.y));
        o.w = pack_h2(tanh_fast(eB.x + pB1.x), tanh_fast(eB.y + pB1.y));
        dst[kt * 32] = o;
    }
}

// ================= kernel 3: smem-free fp16 GEMM  out = A @ W + bias =================
// CTA 128(M) x 128(N), 128 threads = 4 warps (2M x 2N), warp tile 64x64.
// 2 CTAs/SM; operands via ld.global.nc (B gets L1 reuse); register double-buffered.
__global__ __launch_bounds__(128, 2) void gemm_kernel(
    const float* __restrict__ b_out, float* __restrict__ out) {
    __shared__ float bias_s[128];

    int tid = threadIdx.x;
    int lane = tid & 31;
    int wid = tid >> 5;       // 0..3
    int wm = wid >> 1;        // 0..1
    int wn = wid & 1;         // 0..1

    int n0 = blockIdx.x << 7;          // N-tile (fast dim -> A reuse in L2)
    int m0 = blockIdx.y << 7;          // M-tile

    bias_s[tid] = b_out[n0 + tid];
    __syncthreads();

    int mt_base = (m0 >> 4) + wm * 4;
    int nt_base = (n0 >> 4) + wn * 4;
    const uint4* aP[4];
    const uint4* bP[4];
#pragma unroll
    for (int i = 0; i < 4; ++i)
        aP[i] = g_Aft + ((size_t)(mt_base + i) << 11) + lane;   // * (64 tiles * 32 lanes)
#pragma unroll
    for (int g = 0; g < 4; ++g)
        bP[g] = g_Bft + ((size_t)(nt_base + g) << 11) + lane;

    float acc[4][8][4];
#pragma unroll
    for (int mt = 0; mt < 4; ++mt)
#pragma unroll
        for (int nt = 0; nt < 8; ++nt)
#pragma unroll
            for (int q = 0; q < 4; ++q) acc[mt][nt][q] = 0.0f;

    uint4 A0[4][2], B0[4][2], A1[4][2], B1[4][2];

#define LOADC(c, Ab, Bb)                                   \
    do {                                                   \
        int _o = (c) * 64;                                 \
        _Pragma("unroll")                                  \
        for (int i = 0; i < 4; ++i) {                      \
            Ab[i][0] = ldg_nc(aP[i] + _o);                 \
            Ab[i][1] = ldg_nc(aP[i] + _o + 32);            \
        }                                                  \
        _Pragma("unroll")                                  \
        for (int g = 0; g < 4; ++g) {                      \
            Bb[g][0] = ldg_nc(bP[g] + _o);                 \
            Bb[g][1] = ldg_nc(bP[g] + _o + 32);            \
        }                                                  \
    } while (0)

#define COMPUTE(Ab, Bb)                                                         \
    do {                                                                        \
        _Pragma("unroll")                                                       \
        for (int ks = 0; ks < 2; ++ks) {                                        \
            _Pragma("unroll")                                                   \
            for (int i = 0; i < 4; ++i) {                                       \
                _Pragma("unroll")                                               \
                for (int g = 0; g < 4; ++g) {                                   \
                    mma_fp16(acc[i][g * 2][0], acc[i][g * 2][1],                \
                             acc[i][g * 2][2], acc[i][g * 2][3],                \
                             Ab[i][ks].x, Ab[i][ks].y, Ab[i][ks].z, Ab[i][ks].w,\
                             Bb[g][ks].x, Bb[g][ks].y);                         \
                    mma_fp16(acc[i][g * 2 + 1][0], acc[i][g * 2 + 1][1],        \
                             acc[i][g * 2 + 1][2], acc[i][g * 2 + 1][3],        \
                             Ab[i][ks].x, Ab[i][ks].y, Ab[i][ks].z, Ab[i][ks].w,\
                             Bb[g][ks].z, Bb[g][ks].w);                         \
                }                                                               \
            }                                                                   \
        }                                                                       \
    } while (0)

    LOADC(0, A0, B0);
#pragma unroll 1
    for (int c = 0; c < 32; c += 2) {
        if (c + 1 < 32) LOADC(c + 1, A1, B1);
        COMPUTE(A0, B0);
        if (c + 2 < 32) LOADC(c + 2, A0, B0);
        COMPUTE(A1, B1);
    }
#undef LOADC
#undef COMPUTE

    // ---- epilogue: bias + store ----
    int gr = lane >> 2, gc2 = (lane & 3) * 2;
    const float* bias_w = bias_s + wn * 64;
#pragma unroll
    for (int mt = 0; mt < 4; ++mt) {
#pragma unroll
        for (int half = 0; half < 2; ++half) {
            int row = m0 + wm * 64 + mt * 16 + gr + half * 8;
            float* orow = out + (size_t)row * Vdim + n0 + wn * 64;
#pragma unroll
            for (int nt = 0; nt < 8; ++nt) {
                int col = nt * 8 + gc2;
                float2 v;
                v.x = acc[mt][nt][half * 2 + 0] + bias_w[col];
                v.y = acc[mt][nt][half * 2 + 1] + bias_w[col + 1];
                *(float2*)(orow + col) = v;
            }
        }
    }
}

// ================= launch =================
extern "C" void kernel_launch(void* const* d_in, const int* in_sizes, int n_in,
                              void* d_out, int out_size) {
    const float* enc    = (const float*)d_in[0];
    const float* pred   = (const float*)d_in[1];
    const float* W_enc  = (const float*)d_in[2];
    const float* b_enc  = (const float*)d_in[3];
    const float* W_pred = (const float*)d_in[4];
    const float* b_pred = (const float*)d_in[5];
    const float* W_out  = (const float*)d_in[6];
    const float* b_out  = (const float*)d_in[7];
    float* out = (float*)d_out;

    // merged: enc proj (256 CTAs) + pred proj (64) + W_out fragment pack (32)
    prep_kernel<<<352, 256>>>(enc, W_enc, b_enc, pred, W_pred, b_pred, W_out);
    // A = tanh(enc_out (+) pred_out) -> fragment tiles
    tanh_frag_kernel<<<NMT, 128>>>();
    // smem-free fragment GEMM: CTA 128x128, 2 CTAs/SM
    gemm_kernel<<<dim3(8, 512), 128>>>(b_out, out);
}